// round 16
// baseline (speedup 1.0000x reference)
#include <cuda_runtime.h>
#include <cstdint>
#include <math.h>

#define BB 4
#define SS 2048
#define DD 1024
#define HH 16
#define HDIM 64
#define MM (BB*SS)   /* 8192 */

// Scratch (device globals — no allocations allowed)
__device__ float g_Q [BB*SS*DD];
__device__ float g_K [BB*SS*DD];
__device__ float g_V [BB*SS*DD];
__device__ float g_AO[BB*SS*DD];
// tf32-pre-rounded copies of inputs (cp.async feeds raw bits to mma)
__device__ float g_xq[MM*DD];
__device__ float g_xk[MM*DD];
__device__ float g_xv[MM*DD];
__device__ float g_wq[DD*DD];
__device__ float g_wk[DD*DD];
__device__ float g_wv[DD*DD];
__device__ float g_wo[DD*DD];

// ---------------------------------------------------------------------------
// helpers (plain PTX ISA — no sm_103a-gated features)
// ---------------------------------------------------------------------------
static __device__ __forceinline__ uint32_t f2tf(float x) {
    uint32_t u;
    asm("cvt.rna.tf32.f32 %0, %1;" : "=r"(u) : "f"(x));
    return u;
}
static __device__ __forceinline__ void mma8(float* c, const uint32_t* a,
                                            const uint32_t* b) {
    asm volatile(
        "mma.sync.aligned.m16n8k8.row.col.f32.tf32.tf32.f32 "
        "{%0,%1,%2,%3}, {%4,%5,%6,%7}, {%8,%9}, {%0,%1,%2,%3};"
        : "+f"(c[0]), "+f"(c[1]), "+f"(c[2]), "+f"(c[3])
        : "r"(a[0]), "r"(a[1]), "r"(a[2]), "r"(a[3]), "r"(b[0]), "r"(b[1]));
}
static __device__ __forceinline__ uint32_t smem_u32(const void* p) {
    uint32_t a;
    asm("{ .reg .u64 t; cvta.to.shared.u64 t, %1; cvt.u32.u64 %0, t; }"
        : "=r"(a) : "l"(p));
    return a;
}
static __device__ __forceinline__ void cp_async16(uint32_t d, const void* g) {
    asm volatile("cp.async.cg.shared.global [%0], [%1], 16;"
                 :: "r"(d), "l"(g) : "memory");
}
static __device__ __forceinline__ void ldsm4(uint32_t* r, uint32_t addr) {
    asm volatile("ldmatrix.sync.aligned.m8n8.x4.shared.b16 {%0,%1,%2,%3}, [%4];"
                 : "=r"(r[0]), "=r"(r[1]), "=r"(r[2]), "=r"(r[3]) : "r"(addr));
}

// ---------------------------------------------------------------------------
// Pre-round all GEMM inputs to tf32 (RNA). ~224MB traffic, memory-bound.
// ---------------------------------------------------------------------------
static __device__ __forceinline__ float4 rf4(float4 a) {
    a.x = __uint_as_float(f2tf(a.x));
    a.y = __uint_as_float(f2tf(a.y));
    a.z = __uint_as_float(f2tf(a.z));
    a.w = __uint_as_float(f2tf(a.w));
    return a;
}
#define BIGF4 (MM*DD/4)   /* 2097152 */
#define SMF4  (DD*DD/4)   /* 262144  */
#define ROUND_TOTAL (3*BIGF4 + 4*SMF4)

__global__ __launch_bounds__(256) void round_all(
    const float* __restrict__ q, const float* __restrict__ k,
    const float* __restrict__ v, const float* __restrict__ wq,
    const float* __restrict__ wk, const float* __restrict__ wv,
    const float* __restrict__ wo)
{
    int i = blockIdx.x * 256 + threadIdx.x;
    if (i >= ROUND_TOTAL) return;
    if (i < 3 * BIGF4) {
        int r = i / BIGF4, o = i - r * BIGF4;
        const float4* s = (const float4*)(r == 0 ? q : r == 1 ? k : v);
        float4* d = (float4*)(r == 0 ? g_xq : r == 1 ? g_xk : g_xv);
        d[o] = rf4(s[o]);
    } else {
        int j = i - 3 * BIGF4;
        int r = j / SMF4, o = j - r * SMF4;
        const float4* s = (const float4*)(r == 0 ? wq : r == 1 ? wk :
                                          r == 2 ? wv : wo);
        float4* d = (float4*)(r == 0 ? g_wq : r == 1 ? g_wk :
                              r == 2 ? g_wv : g_wo);
        d[o] = rf4(s[o]);
    }
}

// ---------------------------------------------------------------------------
// GEMM v2: C[M,N] = alpha * A[M,K] * W[N,K]^T (+ bias), tf32 mma.sync.
// CTA 128x128, 128 threads = 4 warps x 64x64 tiles. K-chunk 16.
// 4-stage cp.async pipeline (inputs pre-rounded), ldmatrix fragment loads.
// LDA2=20 words: LDSM tile rows hit distinct banks (20r mod 32 all-distinct).
// Pipeline safety: issue chunk kc+2 touches buffer (kc+2)%4 == (kc-2)%4;
// the barrier in iter kc-1 guarantees every warp finished compute kc-2.
// ---------------------------------------------------------------------------
#define LDA2 20
#define STG2 (2 * 128 * LDA2)        /* words per stage: A + W = 5120 */
#define NST 4
#define G2_SMEM (NST * STG2 * 4)     /* 81920 B */

#define G2_ISSUE(kc, st)                                                      \
    do {                                                                      \
        uint32_t base_ = sb + (st) * (STG2 * 4);                              \
        _Pragma("unroll")                                                     \
        for (int i_ = 0; i_ < 4; i_++) {                                      \
            int cid_ = i_ * 128 + tid;                                        \
            int r_ = cid_ >> 2, c_ = cid_ & 3;                                \
            cp_async16(base_ + (r_ * LDA2 + c_ * 4) * 4,                      \
                       A + (size_t)(m0 + r_) * DD + (kc) * 16 + c_ * 4);      \
            cp_async16(base_ + (128 * LDA2 + r_ * LDA2 + c_ * 4) * 4,         \
                       W + (size_t)(n0 + r_) * DD + (kc) * 16 + c_ * 4);      \
        }                                                                     \
        asm volatile("cp.async.commit_group;" ::: "memory");                  \
    } while (0)

__global__ __launch_bounds__(128) void gemm2(
    const float* __restrict__ A0, const float* __restrict__ W0, float* C0, float al0,
    const float* __restrict__ A1, const float* __restrict__ W1, float* C1, float al1,
    const float* __restrict__ A2, const float* __restrict__ W2, float* C2, float al2,
    const float* __restrict__ bias, int roundC)
{
    extern __shared__ uint32_t gsm[];

    const float* A; const float* W; float* C; float alpha;
    if (blockIdx.z == 0)      { A = A0; W = W0; C = C0; alpha = al0; }
    else if (blockIdx.z == 1) { A = A1; W = W1; C = C1; alpha = al1; }
    else                      { A = A2; W = W2; C = C2; alpha = al2; }

    const int tid  = threadIdx.x;
    const int w    = tid >> 5;
    const int lane = tid & 31;
    const int ly   = lane >> 2;
    const int lx   = lane & 3;
    const int m0   = blockIdx.y * 128;
    const int n0   = blockIdx.x * 128;
    const int wm   = (w & 1) * 64;
    const int wn   = (w >> 1) * 64;
    const uint32_t sb = smem_u32(gsm);

    // ldmatrix per-lane word offsets (within a stage)
    const int a_off = (wm + (lane & 15)) * LDA2 + (lane >> 4) * 4;
    const int b_off = 128 * LDA2 +
                      (wn + (lane & 7) + ((lane >> 4) & 1) * 8) * LDA2 +
                      ((lane >> 3) & 1) * 4;

    float acc[4][8][4];
#pragma unroll
    for (int i = 0; i < 4; i++)
#pragma unroll
        for (int j = 0; j < 8; j++)
#pragma unroll
            for (int r = 0; r < 4; r++) acc[i][j][r] = 0.f;

    G2_ISSUE(0, 0);
    G2_ISSUE(1, 1);

    for (int kc = 0; kc < DD / 16; kc++) {
        if (kc + 2 < DD / 16) G2_ISSUE(kc + 2, (kc + 2) & 3);
        else asm volatile("cp.async.commit_group;" ::: "memory");

        asm volatile("cp.async.wait_group 2;" ::: "memory");
        __syncthreads();                       // chunk kc visible to all

        uint32_t base = sb + (kc & 3) * (STG2 * 4);
#pragma unroll
        for (int ks = 0; ks < 2; ks++) {
            const int k0 = ks * 8;
            uint32_t af[4][4];
#pragma unroll
            for (int i = 0; i < 4; i++)
                ldsm4(af[i], base + (a_off + i * 16 * LDA2 + k0) * 4);
#pragma unroll
            for (int jp = 0; jp < 4; jp++) {
                uint32_t bb[4];
                ldsm4(bb, base + (b_off + jp * 16 * LDA2 + k0) * 4);
#pragma unroll
                for (int i = 0; i < 4; i++) {
                    mma8(acc[i][2 * jp],     af[i], bb);
                    mma8(acc[i][2 * jp + 1], af[i], bb + 2);
                }
            }
        }
    }

#pragma unroll
    for (int i = 0; i < 4; i++) {
        int row = m0 + wm + i * 16 + ly;
#pragma unroll
        for (int j = 0; j < 8; j++) {
            int col = n0 + wn + j * 8 + lx * 2;
            float b0 = bias ? bias[col]     : 0.f;
            float b1 = bias ? bias[col + 1] : 0.f;
            float v0 = acc[i][j][0] * alpha + b0;
            float v1 = acc[i][j][1] * alpha + b1;
            float v2 = acc[i][j][2] * alpha + b0;
            float v3 = acc[i][j][3] * alpha + b1;
            if (roundC) {
                v0 = __uint_as_float(f2tf(v0));
                v1 = __uint_as_float(f2tf(v1));
                v2 = __uint_as_float(f2tf(v2));
                v3 = __uint_as_float(f2tf(v3));
            }
            *(float2*)(C + (size_t)row * DD + col)       = make_float2(v0, v1);
            *(float2*)(C + (size_t)(row + 8) * DD + col) = make_float2(v2, v3);
        }
    }
}

// ---------------------------------------------------------------------------
// Flash-attention, tf32 mma.sync, 2x query blocking, no P smem round-trip,
// 32-key halves (register cap), QK b-fragments via ldmatrix (KST=76 rows are
// LDSM-conflict-free: 12r mod 32 all-distinct).
// Output written tf32-pre-rounded so the O-projection can cp.async raw bits.
// ---------------------------------------------------------------------------
#define KST 76
#define VST 68

__global__ __launch_bounds__(128) void attn_mma(
    const float* __restrict__ Q,
    const float* __restrict__ K,
    const float* __restrict__ V,
    float* __restrict__ O)
{
    __shared__ uint32_t Ks[64 * KST];   // 19456 B
    __shared__ uint32_t Vs[64 * VST];   // 17408 B

    const int tid  = threadIdx.x;
    const int w    = tid >> 5;
    const int lane = tid & 31;
    const int ly   = lane >> 2;
    const int lx   = lane & 3;
    const int qw   = w * 32;
    const int qt   = blockIdx.x;
    const int bh   = blockIdx.y;
    const int b    = bh >> 4;
    const int h    = bh & 15;
    const uint32_t ksb = smem_u32(Ks);

    // ldmatrix per-lane word offset for QK b-frags (pair stride 16 rows)
    const int kb_off = ((lane & 7) + ((lane >> 4) & 1) * 8) * KST +
                       ((lane >> 3) & 1) * 4;

    const float* Qg = Q + ((size_t)b * SS + qt * 128) * DD + h * HDIM;
    const float* Kg = K + (size_t)b * SS * DD + h * HDIM;
    const float* Vg = V + (size_t)b * SS * DD + h * HDIM;
    float*       Og = O + ((size_t)b * SS + qt * 128) * DD + h * HDIM;

    uint32_t aq[2][8][4];
#pragma unroll
    for (int u = 0; u < 2; u++)
#pragma unroll
        for (int ks = 0; ks < 8; ks++) {
            const float* qp = Qg + (size_t)(qw + 16 * u + ly) * DD + ks * 8 + lx;
            aq[u][ks][0] = __float_as_uint(qp[0]);
            aq[u][ks][1] = __float_as_uint(qp[(size_t)8 * DD]);
            aq[u][ks][2] = __float_as_uint(qp[4]);
            aq[u][ks][3] = __float_as_uint(qp[(size_t)8 * DD + 4]);
        }

    float o[2][8][4];
    float m[2][2], l[2][2];
#pragma unroll
    for (int u = 0; u < 2; u++) {
        m[u][0] = m[u][1] = -1e30f;
        l[u][0] = l[u][1] = 0.f;
#pragma unroll
        for (int j = 0; j < 8; j++)
#pragma unroll
            for (int r = 0; r < 4; r++) o[u][j][r] = 0.f;
    }

    for (int t = 0; t < SS / 64; t++) {
#pragma unroll
        for (int it = 0; it < 8; it++) {
            int idx = it * 128 + tid;
            int c = idx >> 4, d4 = (idx & 15) << 2;
            *(float4*)(Ks + c * KST + d4) =
                *(const float4*)(Kg + (size_t)(t * 64 + c) * DD + d4);
            *(float4*)(Vs + c * VST + d4) =
                *(const float4*)(Vg + (size_t)(t * 64 + c) * DD + d4);
        }
        __syncthreads();

#pragma unroll
        for (int half = 0; half < 2; half++) {
            const int kb = half * 32;

            float s[2][4][4];
#pragma unroll
            for (int u = 0; u < 2; u++)
#pragma unroll
                for (int j = 0; j < 4; j++)
#pragma unroll
                    for (int r = 0; r < 4; r++) s[u][j][r] = 0.f;

#pragma unroll
            for (int ks = 0; ks < 8; ks++) {
#pragma unroll
                for (int jp = 0; jp < 2; jp++) {
                    uint32_t bb[4];
                    ldsm4(bb, ksb + ((kb + 16 * jp) * KST + kb_off +
                                     8 * ks) * 4);
                    mma8(s[0][2 * jp],     aq[0][ks], bb);
                    mma8(s[0][2 * jp + 1], aq[0][ks], bb + 2);
                    mma8(s[1][2 * jp],     aq[1][ks], bb);
                    mma8(s[1][2 * jp + 1], aq[1][ks], bb + 2);
                }
            }

#pragma unroll
            for (int u = 0; u < 2; u++) {
                float mx0 = -1e30f, mx1 = -1e30f;
#pragma unroll
                for (int j = 0; j < 4; j++) {
                    mx0 = fmaxf(mx0, fmaxf(s[u][j][0], s[u][j][1]));
                    mx1 = fmaxf(mx1, fmaxf(s[u][j][2], s[u][j][3]));
                }
                mx0 = fmaxf(mx0, __shfl_xor_sync(0xffffffffu, mx0, 1));
                mx0 = fmaxf(mx0, __shfl_xor_sync(0xffffffffu, mx0, 2));
                mx1 = fmaxf(mx1, __shfl_xor_sync(0xffffffffu, mx1, 1));
                mx1 = fmaxf(mx1, __shfl_xor_sync(0xffffffffu, mx1, 2));
                float nm0 = fmaxf(m[u][0], mx0), nm1 = fmaxf(m[u][1], mx1);
                float c0 = __expf(m[u][0] - nm0), c1 = __expf(m[u][1] - nm1);
                m[u][0] = nm0; m[u][1] = nm1;
                float rs0 = 0.f, rs1 = 0.f;
#pragma unroll
                for (int j = 0; j < 4; j++) {
                    s[u][j][0] = __expf(s[u][j][0] - nm0);
                    s[u][j][1] = __expf(s[u][j][1] - nm0);
                    s[u][j][2] = __expf(s[u][j][2] - nm1);
                    s[u][j][3] = __expf(s[u][j][3] - nm1);
                    rs0 += s[u][j][0] + s[u][j][1];
                    rs1 += s[u][j][2] + s[u][j][3];
                }
                rs0 += __shfl_xor_sync(0xffffffffu, rs0, 1);
                rs0 += __shfl_xor_sync(0xffffffffu, rs0, 2);
                rs1 += __shfl_xor_sync(0xffffffffu, rs1, 1);
                rs1 += __shfl_xor_sync(0xffffffffu, rs1, 2);
                l[u][0] = l[u][0] * c0 + rs0;
                l[u][1] = l[u][1] * c1 + rs1;
#pragma unroll
                for (int j = 0; j < 8; j++) {
                    o[u][j][0] *= c0; o[u][j][1] *= c0;
                    o[u][j][2] *= c1; o[u][j][3] *= c1;
                }
            }

            // O += P V : s regs become A-fragments (permuted key order);
            // V rows (2lx, 2lx+1) match the permutation.
#pragma unroll
            for (int ks = 0; ks < 4; ks++) {
                uint32_t pa0[4], pa1[4];
                pa0[0] = f2tf(s[0][ks][0]); pa0[1] = f2tf(s[0][ks][2]);
                pa0[2] = f2tf(s[0][ks][1]); pa0[3] = f2tf(s[0][ks][3]);
                pa1[0] = f2tf(s[1][ks][0]); pa1[1] = f2tf(s[1][ks][2]);
                pa1[2] = f2tf(s[1][ks][1]); pa1[3] = f2tf(s[1][ks][3]);
#pragma unroll
                for (int j = 0; j < 8; j++) {
                    uint32_t bf[2];
                    int bb2 = (kb + 8 * ks + 2 * lx) * VST + ly + 8 * j;
                    bf[0] = Vs[bb2];
                    bf[1] = Vs[bb2 + VST];
                    mma8(o[0][j], pa0, bf);
                    mma8(o[1][j], pa1, bf);
                }
            }
        }
        __syncthreads();
    }

    // ---- normalize + tf32-round + write (O-proj consumes raw bits)
#pragma unroll
    for (int u = 0; u < 2; u++) {
        float i0 = 1.f / l[u][0], i1 = 1.f / l[u][1];
        int r0 = qw + 16 * u + ly;
#pragma unroll
        for (int j = 0; j < 8; j++) {
            float2 v0 = make_float2(
                __uint_as_float(f2tf(o[u][j][0] * i0)),
                __uint_as_float(f2tf(o[u][j][1] * i0)));
            float2 v1 = make_float2(
                __uint_as_float(f2tf(o[u][j][2] * i1)),
                __uint_as_float(f2tf(o[u][j][3] * i1)));
            *(float2*)(Og + (size_t)r0 * DD + 8 * j + 2 * lx)       = v0;
            *(float2*)(Og + (size_t)(r0 + 8) * DD + 8 * j + 2 * lx) = v1;
        }
    }
}

// ---------------------------------------------------------------------------
extern "C" void kernel_launch(void* const* d_in, const int* in_sizes, int n_in,
                              void* d_out, int out_size)
{
    const float* q  = (const float*)d_in[0];
    const float* k  = (const float*)d_in[1];
    const float* v  = (const float*)d_in[2];
    const float* Wq = (const float*)d_in[3];
    const float* Wk = (const float*)d_in[4];
    const float* Wv = (const float*)d_in[5];
    const float* Wo = (const float*)d_in[6];
    const float* bo = (const float*)d_in[7];
    float* out = (float*)d_out;

    void *pQ, *pK, *pV, *pAO, *pxq, *pxk, *pxv, *pwq, *pwk, *pwv, *pwo;
    cudaGetSymbolAddress(&pQ,  g_Q);
    cudaGetSymbolAddress(&pK,  g_K);
    cudaGetSymbolAddress(&pV,  g_V);
    cudaGetSymbolAddress(&pAO, g_AO);
    cudaGetSymbolAddress(&pxq, g_xq);
    cudaGetSymbolAddress(&pxk, g_xk);
    cudaGetSymbolAddress(&pxv, g_xv);
    cudaGetSymbolAddress(&pwq, g_wq);
    cudaGetSymbolAddress(&pwk, g_wk);
    cudaGetSymbolAddress(&pwv, g_wv);
    cudaGetSymbolAddress(&pwo, g_wo);

    cudaFuncSetAttribute(gemm2, cudaFuncAttributeMaxDynamicSharedMemorySize,
                         G2_SMEM);

    // 1) pre-round all GEMM inputs to tf32 (RNA)
    round_all<<<(ROUND_TOTAL + 255) / 256, 256>>>(q, k, v, Wq, Wk, Wv, Wo);

    // 2) fused Q/K/V projections (scale 1/32 in Q); outputs tf32-rounded
    dim3 gg3(DD / 128, MM / 128, 3);
    gemm2<<<gg3, 128, G2_SMEM>>>(
        (const float*)pxq, (const float*)pwq, (float*)pQ, 0.03125f,
        (const float*)pxk, (const float*)pwk, (float*)pK, 1.0f,
        (const float*)pxv, (const float*)pwv, (float*)pV, 1.0f, nullptr, 1);

    // 3) attention (writes tf32-rounded AO)
    dim3 ga(SS / 128, BB * HH);
    attn_mma<<<ga, 128>>>((const float*)pQ, (const float*)pK,
                          (const float*)pV, (float*)pAO);

    // 4) output projection
    dim3 gg(DD / 128, MM / 128, 1);
    gemm2<<<gg, 128, G2_SMEM>>>(
        (const float*)pAO, (const float*)pwo, out, 1.0f,
        nullptr, nullptr, nullptr, 0.f,
        nullptr, nullptr, nullptr, 0.f, bo, 0);
}

// round 17
// speedup vs baseline: 1.0167x; 1.0167x over previous
#include <cuda_runtime.h>
#include <cstdint>
#include <math.h>

#define BB 4
#define SS 2048
#define DD 1024
#define HH 16
#define HDIM 64
#define MM (BB*SS)   /* 8192 */

// Scratch (device globals — no allocations allowed)
__device__ float g_Q [BB*SS*DD];
__device__ float g_K [BB*SS*DD];
__device__ float g_V [BB*SS*DD];
__device__ float g_AO[BB*SS*DD];

// ---------------------------------------------------------------------------
// helpers (plain PTX ISA — no sm_103a-gated features)
// ---------------------------------------------------------------------------
static __device__ __forceinline__ uint32_t f2tf(float x) {
    uint32_t u;
    asm("cvt.rna.tf32.f32 %0, %1;" : "=r"(u) : "f"(x));
    return u;
}
static __device__ __forceinline__ void mma8(float* c, const uint32_t* a,
                                            const uint32_t* b) {
    asm volatile(
        "mma.sync.aligned.m16n8k8.row.col.f32.tf32.tf32.f32 "
        "{%0,%1,%2,%3}, {%4,%5,%6,%7}, {%8,%9}, {%0,%1,%2,%3};"
        : "+f"(c[0]), "+f"(c[1]), "+f"(c[2]), "+f"(c[3])
        : "r"(a[0]), "r"(a[1]), "r"(a[2]), "r"(a[3]), "r"(b[0]), "r"(b[1]));
}
static __device__ __forceinline__ uint32_t smem_u32(const void* p) {
    uint32_t a;
    asm("{ .reg .u64 t; cvta.to.shared.u64 t, %1; cvt.u32.u64 %0, t; }"
        : "=r"(a) : "l"(p));
    return a;
}
static __device__ __forceinline__ void ldsm4(uint32_t* r, uint32_t addr) {
    asm volatile("ldmatrix.sync.aligned.m8n8.x4.shared.b16 {%0,%1,%2,%3}, [%4];"
                 : "=r"(r[0]), "=r"(r[1]), "=r"(r[2]), "=r"(r[3]) : "r"(addr));
}

// ---------------------------------------------------------------------------
// tf32 mma.sync GEMM (round-14 proven skeleton + ldmatrix fragment loads):
// C = alpha * A * W^T (+ bias). CTA 128x128, 256 threads (8 warps x 32x64),
// K-chunk 32, STATIC single-buffer smem (36 KB), register prefetch,
// 2 barriers/chunk, cvt-to-tf32 at STS (no input pre-pass needed).
// LDA=36: scalar STS pattern and LDSM row pattern both conflict-free
// (36 mod 32 = 4 -> 8 consecutive 16B rows cover all 32 banks).
// gridDim.z selects among up to 3 fused problems. roundC -> tf32-round C.
// ---------------------------------------------------------------------------
#define LDA 36

__global__ __launch_bounds__(256) void gemm_mma(
    const float* __restrict__ A0, const float* __restrict__ W0, float* C0, float al0,
    const float* __restrict__ A1, const float* __restrict__ W1, float* C1, float al1,
    const float* __restrict__ A2, const float* __restrict__ W2, float* C2, float al2,
    const float* __restrict__ bias, int roundC)
{
    __shared__ uint32_t As[128 * LDA];
    __shared__ uint32_t Ws[128 * LDA];

    const float* A; const float* W; float* C; float alpha;
    if (blockIdx.z == 0)      { A = A0; W = W0; C = C0; alpha = al0; }
    else if (blockIdx.z == 1) { A = A1; W = W1; C = C1; alpha = al1; }
    else                      { A = A2; W = W2; C = C2; alpha = al2; }

    const int tid  = threadIdx.x;
    const int w    = tid >> 5;
    const int lane = tid & 31;
    const int ly   = lane >> 2;
    const int lx   = lane & 3;
    const int m0   = blockIdx.y * 128;
    const int n0   = blockIdx.x * 128;
    const int wm   = (w & 3) * 32;
    const int wn   = (w >> 2) * 64;

    // ldmatrix lane->address bases (pattern correctness-proven in round 16)
    const uint32_t a0b = smem_u32(As) +
        (((wm + (lane & 15)) * LDA + (lane >> 4) * 4) << 2);
    const uint32_t a1b = a0b + (16 * LDA << 2);
    const uint32_t bbb = smem_u32(Ws) +
        (((wn + (lane & 7) + ((lane >> 4) & 1) * 8) * LDA +
          ((lane >> 3) & 1) * 4) << 2);

    const int lrow = tid >> 3;
    const int lc4  = tid & 7;
    const float* Ap = A + (size_t)(m0 + lrow) * DD + lc4 * 4;
    const float* Wp = W + (size_t)(n0 + lrow) * DD + lc4 * 4;

    float acc[2][8][4];
#pragma unroll
    for (int i = 0; i < 2; i++)
#pragma unroll
        for (int j = 0; j < 8; j++)
#pragma unroll
            for (int r = 0; r < 4; r++) acc[i][j][r] = 0.f;

    float4 ra[4], rw[4];
#pragma unroll
    for (int i = 0; i < 4; i++) {
        ra[i] = *(const float4*)(Ap + (size_t)(32 * i) * DD);
        rw[i] = *(const float4*)(Wp + (size_t)(32 * i) * DD);
    }
#pragma unroll
    for (int i = 0; i < 4; i++) {
        uint32_t* pa = &As[(lrow + 32 * i) * LDA + lc4 * 4];
        pa[0] = f2tf(ra[i].x); pa[1] = f2tf(ra[i].y);
        pa[2] = f2tf(ra[i].z); pa[3] = f2tf(ra[i].w);
        uint32_t* pw = &Ws[(lrow + 32 * i) * LDA + lc4 * 4];
        pw[0] = f2tf(rw[i].x); pw[1] = f2tf(rw[i].y);
        pw[2] = f2tf(rw[i].z); pw[3] = f2tf(rw[i].w);
    }
    __syncthreads();

    for (int kc = 0; kc < DD / 32; kc++) {
        if (kc + 1 < DD / 32) {
            const float* Ap2 = Ap + (kc + 1) * 32;
            const float* Wp2 = Wp + (kc + 1) * 32;
#pragma unroll
            for (int i = 0; i < 4; i++) {
                ra[i] = *(const float4*)(Ap2 + (size_t)(32 * i) * DD);
                rw[i] = *(const float4*)(Wp2 + (size_t)(32 * i) * DD);
            }
        }

#pragma unroll
        for (int ks = 0; ks < 4; ks++) {
            const uint32_t kb4 = (uint32_t)(ks * 8) << 2;
            uint32_t af[2][4];
            ldsm4(af[0], a0b + kb4);
            ldsm4(af[1], a1b + kb4);
#pragma unroll
            for (int jp = 0; jp < 4; jp++) {
                uint32_t bb[4];
                ldsm4(bb, bbb + ((uint32_t)(jp * 16 * LDA) << 2) + kb4);
                mma8(acc[0][2 * jp],     af[0], bb);
                mma8(acc[0][2 * jp + 1], af[0], bb + 2);
                mma8(acc[1][2 * jp],     af[1], bb);
                mma8(acc[1][2 * jp + 1], af[1], bb + 2);
            }
        }
        __syncthreads();

        if (kc + 1 < DD / 32) {
#pragma unroll
            for (int i = 0; i < 4; i++) {
                uint32_t* pa = &As[(lrow + 32 * i) * LDA + lc4 * 4];
                pa[0] = f2tf(ra[i].x); pa[1] = f2tf(ra[i].y);
                pa[2] = f2tf(ra[i].z); pa[3] = f2tf(ra[i].w);
                uint32_t* pw = &Ws[(lrow + 32 * i) * LDA + lc4 * 4];
                pw[0] = f2tf(rw[i].x); pw[1] = f2tf(rw[i].y);
                pw[2] = f2tf(rw[i].z); pw[3] = f2tf(rw[i].w);
            }
            __syncthreads();
        }
    }

#pragma unroll
    for (int i = 0; i < 2; i++) {
        int row = m0 + wm + i * 16 + ly;
#pragma unroll
        for (int j = 0; j < 8; j++) {
            int col = n0 + wn + j * 8 + lx * 2;
            float b0 = bias ? bias[col]     : 0.f;
            float b1 = bias ? bias[col + 1] : 0.f;
            float v0 = acc[i][j][0] * alpha + b0;
            float v1 = acc[i][j][1] * alpha + b1;
            float v2 = acc[i][j][2] * alpha + b0;
            float v3 = acc[i][j][3] * alpha + b1;
            if (roundC) {                 // pre-round for downstream tf32 use
                v0 = __uint_as_float(f2tf(v0));
                v1 = __uint_as_float(f2tf(v1));
                v2 = __uint_as_float(f2tf(v2));
                v3 = __uint_as_float(f2tf(v3));
            }
            *(float2*)(C + (size_t)row * DD + col)       = make_float2(v0, v1);
            *(float2*)(C + (size_t)(row + 8) * DD + col) = make_float2(v2, v3);
        }
    }
}

// ---------------------------------------------------------------------------
// Flash-attention (round-16 verified version): tf32 mma.sync, 2x query
// blocking, 32-key halves, no P smem round-trip, ldmatrix QK b-fragments
// (KST=76: 8 consecutive 16B rows cover all 32 banks -> conflict-free).
// Q/K/V arrive tf32-pre-rounded (raw bit loads). AO written pre-rounded.
// ---------------------------------------------------------------------------
#define KST 76
#define VST 68

__global__ __launch_bounds__(128) void attn_mma(
    const float* __restrict__ Q,
    const float* __restrict__ K,
    const float* __restrict__ V,
    float* __restrict__ O)
{
    __shared__ uint32_t Ks[64 * KST];   // 19456 B
    __shared__ uint32_t Vs[64 * VST];   // 17408 B

    const int tid  = threadIdx.x;
    const int w    = tid >> 5;
    const int lane = tid & 31;
    const int ly   = lane >> 2;
    const int lx   = lane & 3;
    const int qw   = w * 32;
    const int qt   = blockIdx.x;
    const int bh   = blockIdx.y;
    const int b    = bh >> 4;
    const int h    = bh & 15;
    const uint32_t ksb = smem_u32(Ks);

    const int kb_off = ((lane & 7) + ((lane >> 4) & 1) * 8) * KST +
                       ((lane >> 3) & 1) * 4;

    const float* Qg = Q + ((size_t)b * SS + qt * 128) * DD + h * HDIM;
    const float* Kg = K + (size_t)b * SS * DD + h * HDIM;
    const float* Vg = V + (size_t)b * SS * DD + h * HDIM;
    float*       Og = O + ((size_t)b * SS + qt * 128) * DD + h * HDIM;

    uint32_t aq[2][8][4];
#pragma unroll
    for (int u = 0; u < 2; u++)
#pragma unroll
        for (int ks = 0; ks < 8; ks++) {
            const float* qp = Qg + (size_t)(qw + 16 * u + ly) * DD + ks * 8 + lx;
            aq[u][ks][0] = __float_as_uint(qp[0]);
            aq[u][ks][1] = __float_as_uint(qp[(size_t)8 * DD]);
            aq[u][ks][2] = __float_as_uint(qp[4]);
            aq[u][ks][3] = __float_as_uint(qp[(size_t)8 * DD + 4]);
        }

    float o[2][8][4];
    float m[2][2], l[2][2];
#pragma unroll
    for (int u = 0; u < 2; u++) {
        m[u][0] = m[u][1] = -1e30f;
        l[u][0] = l[u][1] = 0.f;
#pragma unroll
        for (int j = 0; j < 8; j++)
#pragma unroll
            for (int r = 0; r < 4; r++) o[u][j][r] = 0.f;
    }

    for (int t = 0; t < SS / 64; t++) {
#pragma unroll
        for (int it = 0; it < 8; it++) {
            int idx = it * 128 + tid;
            int c = idx >> 4, d4 = (idx & 15) << 2;
            *(float4*)(Ks + c * KST + d4) =
                *(const float4*)(Kg + (size_t)(t * 64 + c) * DD + d4);
            *(float4*)(Vs + c * VST + d4) =
                *(const float4*)(Vg + (size_t)(t * 64 + c) * DD + d4);
        }
        __syncthreads();

#pragma unroll
        for (int half = 0; half < 2; half++) {
            const int kb = half * 32;

            float s[2][4][4];
#pragma unroll
            for (int u = 0; u < 2; u++)
#pragma unroll
                for (int j = 0; j < 4; j++)
#pragma unroll
                    for (int r = 0; r < 4; r++) s[u][j][r] = 0.f;

#pragma unroll
            for (int ks = 0; ks < 8; ks++) {
#pragma unroll
                for (int jp = 0; jp < 2; jp++) {
                    uint32_t bb[4];
                    ldsm4(bb, ksb + ((kb + 16 * jp) * KST + kb_off +
                                     8 * ks) * 4);
                    mma8(s[0][2 * jp],     aq[0][ks], bb);
                    mma8(s[0][2 * jp + 1], aq[0][ks], bb + 2);
                    mma8(s[1][2 * jp],     aq[1][ks], bb);
                    mma8(s[1][2 * jp + 1], aq[1][ks], bb + 2);
                }
            }

#pragma unroll
            for (int u = 0; u < 2; u++) {
                float mx0 = -1e30f, mx1 = -1e30f;
#pragma unroll
                for (int j = 0; j < 4; j++) {
                    mx0 = fmaxf(mx0, fmaxf(s[u][j][0], s[u][j][1]));
                    mx1 = fmaxf(mx1, fmaxf(s[u][j][2], s[u][j][3]));
                }
                mx0 = fmaxf(mx0, __shfl_xor_sync(0xffffffffu, mx0, 1));
                mx0 = fmaxf(mx0, __shfl_xor_sync(0xffffffffu, mx0, 2));
                mx1 = fmaxf(mx1, __shfl_xor_sync(0xffffffffu, mx1, 1));
                mx1 = fmaxf(mx1, __shfl_xor_sync(0xffffffffu, mx1, 2));
                float nm0 = fmaxf(m[u][0], mx0), nm1 = fmaxf(m[u][1], mx1);
                float c0 = __expf(m[u][0] - nm0), c1 = __expf(m[u][1] - nm1);
                m[u][0] = nm0; m[u][1] = nm1;
                float rs0 = 0.f, rs1 = 0.f;
#pragma unroll
                for (int j = 0; j < 4; j++) {
                    s[u][j][0] = __expf(s[u][j][0] - nm0);
                    s[u][j][1] = __expf(s[u][j][1] - nm0);
                    s[u][j][2] = __expf(s[u][j][2] - nm1);
                    s[u][j][3] = __expf(s[u][j][3] - nm1);
                    rs0 += s[u][j][0] + s[u][j][1];
                    rs1 += s[u][j][2] + s[u][j][3];
                }
                rs0 += __shfl_xor_sync(0xffffffffu, rs0, 1);
                rs0 += __shfl_xor_sync(0xffffffffu, rs0, 2);
                rs1 += __shfl_xor_sync(0xffffffffu, rs1, 1);
                rs1 += __shfl_xor_sync(0xffffffffu, rs1, 2);
                l[u][0] = l[u][0] * c0 + rs0;
                l[u][1] = l[u][1] * c1 + rs1;
#pragma unroll
                for (int j = 0; j < 8; j++) {
                    o[u][j][0] *= c0; o[u][j][1] *= c0;
                    o[u][j][2] *= c1; o[u][j][3] *= c1;
                }
            }

            // O += P V : s regs become A-fragments (permuted key order);
            // V rows (2lx, 2lx+1) match the permutation.
#pragma unroll
            for (int ks = 0; ks < 4; ks++) {
                uint32_t pa0[4], pa1[4];
                pa0[0] = f2tf(s[0][ks][0]); pa0[1] = f2tf(s[0][ks][2]);
                pa0[2] = f2tf(s[0][ks][1]); pa0[3] = f2tf(s[0][ks][3]);
                pa1[0] = f2tf(s[1][ks][0]); pa1[1] = f2tf(s[1][ks][2]);
                pa1[2] = f2tf(s[1][ks][1]); pa1[3] = f2tf(s[1][ks][3]);
#pragma unroll
                for (int j = 0; j < 8; j++) {
                    uint32_t bf[2];
                    int bb2 = (kb + 8 * ks + 2 * lx) * VST + ly + 8 * j;
                    bf[0] = Vs[bb2];
                    bf[1] = Vs[bb2 + VST];
                    mma8(o[0][j], pa0, bf);
                    mma8(o[1][j], pa1, bf);
                }
            }
        }
        __syncthreads();
    }

    // ---- normalize + tf32-round + write
#pragma unroll
    for (int u = 0; u < 2; u++) {
        float i0 = 1.f / l[u][0], i1 = 1.f / l[u][1];
        int r0 = qw + 16 * u + ly;
#pragma unroll
        for (int j = 0; j < 8; j++) {
            float2 v0 = make_float2(
                __uint_as_float(f2tf(o[u][j][0] * i0)),
                __uint_as_float(f2tf(o[u][j][1] * i0)));
            float2 v1 = make_float2(
                __uint_as_float(f2tf(o[u][j][2] * i1)),
                __uint_as_float(f2tf(o[u][j][3] * i1)));
            *(float2*)(Og + (size_t)r0 * DD + 8 * j + 2 * lx)       = v0;
            *(float2*)(Og + (size_t)(r0 + 8) * DD + 8 * j + 2 * lx) = v1;
        }
    }
}

// ---------------------------------------------------------------------------
extern "C" void kernel_launch(void* const* d_in, const int* in_sizes, int n_in,
                              void* d_out, int out_size)
{
    const float* q  = (const float*)d_in[0];
    const float* k  = (const float*)d_in[1];
    const float* v  = (const float*)d_in[2];
    const float* Wq = (const float*)d_in[3];
    const float* Wk = (const float*)d_in[4];
    const float* Wv = (const float*)d_in[5];
    const float* Wo = (const float*)d_in[6];
    const float* bo = (const float*)d_in[7];
    float* out = (float*)d_out;

    void *pQ, *pK, *pV, *pAO;
    cudaGetSymbolAddress(&pQ,  g_Q);
    cudaGetSymbolAddress(&pK,  g_K);
    cudaGetSymbolAddress(&pV,  g_V);
    cudaGetSymbolAddress(&pAO, g_AO);

    // fused Q/K/V projections (scale 1/32 folded into Q); outputs tf32-rounded
    dim3 gg3(DD / 128, MM / 128, 3);
    gemm_mma<<<gg3, 256>>>(q, Wq, (float*)pQ, 0.03125f,
                           k, Wk, (float*)pK, 1.0f,
                           v, Wv, (float*)pV, 1.0f, nullptr, 1);

    dim3 ga(SS / 128, BB * HH);    // (16, 64)
    attn_mma<<<ga, 128>>>((const float*)pQ, (const float*)pK,
                          (const float*)pV, (float*)pAO);

    dim3 gg(DD / 128, MM / 128, 1);
    gemm_mma<<<gg, 256>>>((const float*)pAO, Wo, out, 1.0f,
                          nullptr, nullptr, nullptr, 0.f,
                          nullptr, nullptr, nullptr, 0.f, bo, 0);
}